// round 7
// baseline (speedup 1.0000x reference)
#include <cuda_runtime.h>
#include <math.h>

#define TTOK 1024
#define DDIM 2048
#define IDIM 1024
#define NEXP 32
#define KSEL 8
#define NGRP 8
#define GSZ  4
#define TOPG 4
#define SCAL 2.5f

// tf32 round-toward-zero: raw truncation (Triton-style fused gate matmul)
__device__ __forceinline__ float tf32z(float x) {
    return __uint_as_float(__float_as_uint(x) & 0xFFFFE000u);
}
// tf32 round-to-nearest (cvt.rna) — cuBLAS conversion path (expert GEMMs)
__device__ __forceinline__ float tf32n(float x) {
    unsigned int u = __float_as_uint(x);
    unsigned int r;
    asm("cvt.rna.tf32.f32 %0, %1;" : "=r"(r) : "r"(u));
    return __uint_as_float(r);
}

// ---------------- scratch (static device globals; no allocation) ----------------
__device__ int   g_cnt[NEXP];
__device__ int   g_off[NEXP];
__device__ int   g_tok[NEXP][TTOK];
__device__ float g_wt [NEXP][TTOK];
__device__ float g_act[(size_t)KSEL * TTOK * IDIM];   // 32 MB
__device__ float g_act_sh[(size_t)TTOK * IDIM];       // 4 MB

// ---------------- tiny utility kernels ----------------
__global__ void zero_kernel() {
    int i = threadIdx.x;
    if (i < NEXP) g_cnt[i] = 0;
}

__global__ void offs_kernel() {
    if (threadIdx.x == 0) {
        int s = 0;
        for (int e = 0; e < NEXP; e++) { g_off[e] = s; s += g_cnt[e]; }
    }
}

// ---------------- gate / routing (RZ-tf32 logits) ----------------
__global__ void gate_kernel(const float* __restrict__ x,
                            const float* __restrict__ gw,
                            const float* __restrict__ ebias)
{
    __shared__ float xs[DDIM];
    __shared__ float sc[NEXP];
    int t = blockIdx.x;
    const float* xr = x + (size_t)t * DDIM;
    for (int d = threadIdx.x; d < DDIM; d += blockDim.x) xs[d] = tf32z(xr[d]);
    __syncthreads();

    int warp = threadIdx.x >> 5, lane = threadIdx.x & 31;
    for (int e = warp; e < NEXP; e += 4) {
        const float* w = gw + (size_t)e * DDIM;
        float s = 0.f;
        for (int d = lane; d < DDIM; d += 32) s += xs[d] * tf32z(w[d]);
        #pragma unroll
        for (int o = 16; o; o >>= 1) s += __shfl_xor_sync(0xffffffffu, s, o);
        if (lane == 0) sc[e] = 1.f / (1.f + expf(-s));
    }
    __syncthreads();

    if (threadIdx.x == 0) {
        float sfc[NEXP];
        #pragma unroll
        for (int e = 0; e < NEXP; e++) sfc[e] = sc[e] + ebias[e];

        float gs[NGRP];
        for (int g = 0; g < NGRP; g++) {
            float vv[4] = { sfc[g*GSZ+0], sfc[g*GSZ+1], sfc[g*GSZ+2], sfc[g*GSZ+3] };
            float m1 = fmaxf(fmaxf(vv[0], vv[1]), fmaxf(vv[2], vv[3]));
            float s2 = -1e30f; bool used = false;
            for (int j = 0; j < 4; j++) {
                if (!used && vv[j] == m1) { used = true; continue; }
                s2 = fmaxf(s2, vv[j]);
            }
            gs[g] = m1 + s2;
        }

        bool gmask[NGRP];
        for (int g = 0; g < NGRP; g++) gmask[g] = false;
        for (int k = 0; k < TOPG; k++) {
            int bi = -1; float bv = -1e30f;
            for (int g = 0; g < NGRP; g++)
                if (!gmask[g] && gs[g] > bv) { bv = gs[g]; bi = g; }
            gmask[bi] = true;
        }

        float mv[NEXP];
        for (int e = 0; e < NEXP; e++) mv[e] = gmask[e / GSZ] ? sfc[e] : 0.f;

        int   idx[KSEL]; float tw[KSEL]; float tsum = 0.f;
        for (int k = 0; k < KSEL; k++) {
            int bi = 0; float bv = -1e30f;
            for (int e = 0; e < NEXP; e++)
                if (mv[e] > bv) { bv = mv[e]; bi = e; }
            mv[bi] = -1e30f;
            idx[k] = bi;
            tw[k]  = sc[bi];
            tsum  += sc[bi];
        }
        float inv = SCAL / (tsum + 1e-20f);
        for (int k = 0; k < KSEL; k++) {
            int e = idx[k];
            int slot = atomicAdd(&g_cnt[e], 1);
            g_tok[e][slot] = t;
            g_wt [e][slot] = tw[k] * inv;
        }
    }
}

// ---------------- phase A: SwiGLU up ----------
// ALL expert GEMMs (shared + routed): RNA-tf32 inputs, fp32 accumulate.
template<bool SHARED>
__global__ void __launch_bounds__(256)
swiglu_kernel(const float* __restrict__ x,
              const float* __restrict__ w1,
              const float* __restrict__ w3,
              float* __restrict__ actout_sh)
{
    int e   = SHARED ? 0 : blockIdx.z;
    int cnt = SHARED ? TTOK : g_cnt[e];
    int m0  = blockIdx.y * 64;
    if (m0 >= cnt) return;
    int n0  = blockIdx.x * 64;

    const float* W1 = w1 + (SHARED ? 0 : (size_t)e * IDIM * DDIM);
    const float* W3 = w3 + (SHARED ? 0 : (size_t)e * IDIM * DDIM);
    float* actout = SHARED ? actout_sh : (g_act + (size_t)g_off[e] * IDIM);

    __shared__ float As[16][64];
    __shared__ float B1[16][64];
    __shared__ float B3[16][64];

    int tid = threadIdx.x;
    int tx = tid & 15, ty = tid >> 4;
    int lr = tid >> 2;
    int lk = (tid & 3) * 4;

    bool avalid = (m0 + lr < cnt);
    int tokr = 0;
    if (avalid) tokr = SHARED ? (m0 + lr) : g_tok[e][m0 + lr];
    const float* arow = x + (size_t)tokr * DDIM;

    float acc1[4][4] = {}, acc3[4][4] = {};

    for (int k0 = 0; k0 < DDIM; k0 += 16) {
        float4 a4 = avalid ? *(const float4*)(arow + k0 + lk) : make_float4(0.f,0.f,0.f,0.f);
        float4 b1 = *(const float4*)(W1 + (size_t)(n0 + lr) * DDIM + k0 + lk);
        float4 b3 = *(const float4*)(W3 + (size_t)(n0 + lr) * DDIM + k0 + lk);
        __syncthreads();
        As[lk+0][lr] = tf32n(a4.x); As[lk+1][lr] = tf32n(a4.y);
        As[lk+2][lr] = tf32n(a4.z); As[lk+3][lr] = tf32n(a4.w);
        B1[lk+0][lr] = tf32n(b1.x); B1[lk+1][lr] = tf32n(b1.y);
        B1[lk+2][lr] = tf32n(b1.z); B1[lk+3][lr] = tf32n(b1.w);
        B3[lk+0][lr] = tf32n(b3.x); B3[lk+1][lr] = tf32n(b3.y);
        B3[lk+2][lr] = tf32n(b3.z); B3[lk+3][lr] = tf32n(b3.w);
        __syncthreads();
        #pragma unroll
        for (int k = 0; k < 16; k++) {
            float4 av  = *(const float4*)&As[k][ty * 4];
            float4 bv1 = *(const float4*)&B1[k][tx * 4];
            float4 bv3 = *(const float4*)&B3[k][tx * 4];
            float a[4]  = {av.x, av.y, av.z, av.w};
            float c1[4] = {bv1.x, bv1.y, bv1.z, bv1.w};
            float c3[4] = {bv3.x, bv3.y, bv3.z, bv3.w};
            #pragma unroll
            for (int i = 0; i < 4; i++)
                #pragma unroll
                for (int j = 0; j < 4; j++) {
                    acc1[i][j] = fmaf(a[i], c1[j], acc1[i][j]);
                    acc3[i][j] = fmaf(a[i], c3[j], acc3[i][j]);
                }
        }
    }

    #pragma unroll
    for (int i = 0; i < 4; i++) {
        int m = m0 + ty * 4 + i;
        if (m < cnt) {
            float v[4];
            #pragma unroll
            for (int j = 0; j < 4; j++) {
                float gv = acc1[i][j];
                float sg = 1.f / (1.f + expf(-gv));
                v[j] = gv * sg * acc3[i][j];
            }
            *(float4*)(actout + (size_t)m * IDIM + n0 + tx * 4) =
                make_float4(v[0], v[1], v[2], v[3]);
        }
    }
}

// ---------------- phase B: down proj + weighted combine (RNA-tf32) --------------
template<bool SHARED>
__global__ void __launch_bounds__(256)
down_kernel(const float* __restrict__ w2, float* __restrict__ out)
{
    int e   = SHARED ? 0 : blockIdx.z;
    int cnt = SHARED ? TTOK : g_cnt[e];
    int m0  = blockIdx.y * 64;
    if (m0 >= cnt) return;
    int n0  = blockIdx.x * 64;

    const float* W2    = w2 + (SHARED ? 0 : (size_t)e * DDIM * IDIM);
    const float* actin = SHARED ? g_act_sh : (g_act + (size_t)g_off[e] * IDIM);

    __shared__ float As[16][64];
    __shared__ float Bs[16][64];

    int tid = threadIdx.x;
    int tx = tid & 15, ty = tid >> 4;
    int lr = tid >> 2;
    int lk = (tid & 3) * 4;

    bool avalid = (m0 + lr < cnt);
    const float* arow = actin + (size_t)(m0 + lr) * IDIM;

    float acc[4][4] = {};

    for (int k0 = 0; k0 < IDIM; k0 += 16) {
        float4 a4 = avalid ? *(const float4*)(arow + k0 + lk) : make_float4(0.f,0.f,0.f,0.f);
        float4 b4 = *(const float4*)(W2 + (size_t)(n0 + lr) * IDIM + k0 + lk);
        __syncthreads();
        As[lk+0][lr] = tf32n(a4.x); As[lk+1][lr] = tf32n(a4.y);
        As[lk+2][lr] = tf32n(a4.z); As[lk+3][lr] = tf32n(a4.w);
        Bs[lk+0][lr] = tf32n(b4.x); Bs[lk+1][lr] = tf32n(b4.y);
        Bs[lk+2][lr] = tf32n(b4.z); Bs[lk+3][lr] = tf32n(b4.w);
        __syncthreads();
        #pragma unroll
        for (int k = 0; k < 16; k++) {
            float4 av = *(const float4*)&As[k][ty * 4];
            float4 bv = *(const float4*)&Bs[k][tx * 4];
            float a[4] = {av.x, av.y, av.z, av.w};
            float b[4] = {bv.x, bv.y, bv.z, bv.w};
            #pragma unroll
            for (int i = 0; i < 4; i++)
                #pragma unroll
                for (int j = 0; j < 4; j++)
                    acc[i][j] = fmaf(a[i], b[j], acc[i][j]);
        }
    }

    #pragma unroll
    for (int i = 0; i < 4; i++) {
        int m = m0 + ty * 4 + i;
        if (m >= cnt) continue;
        if (SHARED) {
            float* orow = out + (size_t)m * DDIM + n0 + tx * 4;
            *(float4*)orow = make_float4(acc[i][0], acc[i][1], acc[i][2], acc[i][3]);
        } else {
            int tok  = g_tok[e][m];
            float wt = g_wt[e][m];
            float* orow = out + (size_t)tok * DDIM + n0 + tx * 4;
            #pragma unroll
            for (int j = 0; j < 4; j++) atomicAdd(orow + j, wt * acc[i][j]);
        }
    }
}

// ---------------- launch ----------------
extern "C" void kernel_launch(void* const* d_in, const int* in_sizes, int n_in,
                              void* d_out, int out_size)
{
    const float* x   = (const float*)d_in[0];
    const float* gw  = (const float*)d_in[1];
    const float* eb  = (const float*)d_in[2];
    const float* w1  = (const float*)d_in[3];
    const float* w2  = (const float*)d_in[4];
    const float* w3  = (const float*)d_in[5];
    const float* sw1 = (const float*)d_in[6];
    const float* sw2 = (const float*)d_in[7];
    const float* sw3 = (const float*)d_in[8];
    float* out = (float*)d_out;

    float* act_sh_ptr = nullptr;
    cudaGetSymbolAddress((void**)&act_sh_ptr, g_act_sh);

    zero_kernel<<<1, 32>>>();
    gate_kernel<<<TTOK, 128>>>(x, gw, eb);
    offs_kernel<<<1, 1>>>();

    // shared expert first (plain stores -> initializes out fully)
    swiglu_kernel<true><<<dim3(IDIM / 64, TTOK / 64, 1), 256>>>(x, sw1, sw3, act_sh_ptr);
    down_kernel<true><<<dim3(DDIM / 64, TTOK / 64, 1), 256>>>(sw2, out);

    // routed experts (atomicAdd on top)
    swiglu_kernel<false><<<dim3(IDIM / 64, TTOK / 64, NEXP), 256>>>(x, w1, w3, nullptr);
    down_kernel<false><<<dim3(DDIM / 64, TTOK / 64, NEXP), 256>>>(w2, out);
}

// round 8
// speedup vs baseline: 3.0218x; 3.0218x over previous
#include <cuda_runtime.h>
#include <math.h>

#define TTOK 1024
#define DDIM 2048
#define IDIM 1024
#define NEXP 32
#define KSEL 8
#define NGRP 8
#define GSZ  4
#define TOPG 4
#define SCAL 2.5f
#define LDP  36   // smem leading dim: 4*r+k bank pattern -> conflict-free frags

// tf32 truncation (RZ) — gate logits path
__device__ __forceinline__ float tf32z(float x) {
    return __uint_as_float(__float_as_uint(x) & 0xFFFFE000u);
}
// tf32 RNA as raw bits — expert GEMM operands (cuBLAS-style)
__device__ __forceinline__ unsigned tf32u(float x) {
    unsigned r; asm("cvt.rna.tf32.f32 %0, %1;" : "=r"(r) : "f"(x)); return r;
}

__device__ __forceinline__ void mma8(float c[4], const unsigned a[4], const unsigned b[2]) {
    asm volatile("mma.sync.aligned.m16n8k8.row.col.f32.tf32.tf32.f32 "
        "{%0,%1,%2,%3}, {%4,%5,%6,%7}, {%8,%9}, {%0,%1,%2,%3};"
        : "+f"(c[0]), "+f"(c[1]), "+f"(c[2]), "+f"(c[3])
        : "r"(a[0]), "r"(a[1]), "r"(a[2]), "r"(a[3]), "r"(b[0]), "r"(b[1]));
}

// ---------------- scratch ----------------
__device__ int   g_cnt[NEXP];
__device__ int   g_off[NEXP];
__device__ int   g_tok[NEXP][TTOK];
__device__ float g_wt [NEXP][TTOK];
__device__ float g_act[(size_t)KSEL * TTOK * IDIM];
__device__ float g_act_sh[(size_t)TTOK * IDIM];

__global__ void zero_kernel() {
    int i = threadIdx.x;
    if (i < NEXP) g_cnt[i] = 0;
}
__global__ void offs_kernel() {
    if (threadIdx.x == 0) {
        int s = 0;
        for (int e = 0; e < NEXP; e++) { g_off[e] = s; s += g_cnt[e]; }
    }
}

// ---------------- gate / routing (RZ-tf32 logits) — unchanged from passing R7 ----
__global__ void gate_kernel(const float* __restrict__ x,
                            const float* __restrict__ gw,
                            const float* __restrict__ ebias)
{
    __shared__ float xs[DDIM];
    __shared__ float sc[NEXP];
    int t = blockIdx.x;
    const float* xr = x + (size_t)t * DDIM;
    for (int d = threadIdx.x; d < DDIM; d += blockDim.x) xs[d] = tf32z(xr[d]);
    __syncthreads();

    int warp = threadIdx.x >> 5, lane = threadIdx.x & 31;
    for (int e = warp; e < NEXP; e += 4) {
        const float* w = gw + (size_t)e * DDIM;
        float s = 0.f;
        for (int d = lane; d < DDIM; d += 32) s += xs[d] * tf32z(w[d]);
        #pragma unroll
        for (int o = 16; o; o >>= 1) s += __shfl_xor_sync(0xffffffffu, s, o);
        if (lane == 0) sc[e] = 1.f / (1.f + expf(-s));
    }
    __syncthreads();

    if (threadIdx.x == 0) {
        float sfc[NEXP];
        #pragma unroll
        for (int e = 0; e < NEXP; e++) sfc[e] = sc[e] + ebias[e];

        float gs[NGRP];
        for (int g = 0; g < NGRP; g++) {
            float vv[4] = { sfc[g*GSZ+0], sfc[g*GSZ+1], sfc[g*GSZ+2], sfc[g*GSZ+3] };
            float m1 = fmaxf(fmaxf(vv[0], vv[1]), fmaxf(vv[2], vv[3]));
            float s2 = -1e30f; bool used = false;
            for (int j = 0; j < 4; j++) {
                if (!used && vv[j] == m1) { used = true; continue; }
                s2 = fmaxf(s2, vv[j]);
            }
            gs[g] = m1 + s2;
        }

        bool gmask[NGRP];
        for (int g = 0; g < NGRP; g++) gmask[g] = false;
        for (int k = 0; k < TOPG; k++) {
            int bi = -1; float bv = -1e30f;
            for (int g = 0; g < NGRP; g++)
                if (!gmask[g] && gs[g] > bv) { bv = gs[g]; bi = g; }
            gmask[bi] = true;
        }

        float mv[NEXP];
        for (int e = 0; e < NEXP; e++) mv[e] = gmask[e / GSZ] ? sfc[e] : 0.f;

        int   idx[KSEL]; float tw[KSEL]; float tsum = 0.f;
        for (int k = 0; k < KSEL; k++) {
            int bi = 0; float bv = -1e30f;
            for (int e = 0; e < NEXP; e++)
                if (mv[e] > bv) { bv = mv[e]; bi = e; }
            mv[bi] = -1e30f;
            idx[k] = bi;
            tw[k]  = sc[bi];
            tsum  += sc[bi];
        }
        float inv = SCAL / (tsum + 1e-20f);
        for (int k = 0; k < KSEL; k++) {
            int e = idx[k];
            int slot = atomicAdd(&g_cnt[e], 1);
            g_tok[e][slot] = t;
            g_wt [e][slot] = tw[k] * inv;
        }
    }
}

// ---------------- phase A: SwiGLU up via tensor-core tf32 mma -------------------
// tile 128(m) x 64(n), BK=32, 8 warps each 32x32; RNA-tf32 operands, f32 accum
template<bool SHARED>
__global__ void __launch_bounds__(256)
swiglu_mma(const float* __restrict__ x,
           const float* __restrict__ w1,
           const float* __restrict__ w3,
           float* __restrict__ actout_sh)
{
    int e   = SHARED ? 0 : blockIdx.z;
    int cnt = SHARED ? TTOK : g_cnt[e];
    int m0  = blockIdx.y * 128;
    if (m0 >= cnt) return;
    int n0  = blockIdx.x * 64;

    const float* W1 = w1 + (SHARED ? 0 : (size_t)e * IDIM * DDIM);
    const float* W3 = w3 + (SHARED ? 0 : (size_t)e * IDIM * DDIM);
    float* actout   = SHARED ? actout_sh : (g_act + (size_t)g_off[e] * IDIM);

    __shared__ unsigned As [128][LDP];
    __shared__ unsigned B1s[64][LDP];
    __shared__ unsigned B3s[64][LDP];

    int tid  = threadIdx.x;
    int lane = tid & 31, wid = tid >> 5;
    int wm = (wid & 3) * 32, wn = (wid >> 2) * 32;
    int grp = lane >> 2, qid = lane & 3;

    // A: 4 rows/thread (idx = tid + i*256 -> row idx>>3, col (idx&7)*4)
    const float* aptr[4]; bool aval[4]; int arow[4], acol[4];
    #pragma unroll
    for (int i = 0; i < 4; i++) {
        int idx = tid + i * 256;
        int r = idx >> 3, c = (idx & 7) * 4;
        int m = m0 + r;
        bool v = m < cnt;
        int tok = 0;
        if (v) tok = SHARED ? m : g_tok[e][m];
        aptr[i] = x + (size_t)tok * DDIM + c;
        aval[i] = v; arow[i] = r; acol[i] = c;
    }
    int br = tid >> 3, bc = (tid & 7) * 4;
    const float* b1p0 = W1 + (size_t)(n0 + br) * DDIM + bc;
    const float* b1p1 = b1p0 + (size_t)32 * DDIM;
    const float* b3p0 = W3 + (size_t)(n0 + br) * DDIM + bc;
    const float* b3p1 = b3p0 + (size_t)32 * DDIM;

    float acc1[2][4][4], acc3[2][4][4];
    #pragma unroll
    for (int mt = 0; mt < 2; mt++)
        #pragma unroll
        for (int nt = 0; nt < 4; nt++)
            #pragma unroll
            for (int i = 0; i < 4; i++) { acc1[mt][nt][i] = 0.f; acc3[mt][nt][i] = 0.f; }

    float4 av[4], bv1[2], bv3[2];
    #define SWLOADS(K0) do { \
        av[0] = aval[0] ? *(const float4*)(aptr[0] + (K0)) : make_float4(0.f,0.f,0.f,0.f); \
        av[1] = aval[1] ? *(const float4*)(aptr[1] + (K0)) : make_float4(0.f,0.f,0.f,0.f); \
        av[2] = aval[2] ? *(const float4*)(aptr[2] + (K0)) : make_float4(0.f,0.f,0.f,0.f); \
        av[3] = aval[3] ? *(const float4*)(aptr[3] + (K0)) : make_float4(0.f,0.f,0.f,0.f); \
        bv1[0] = *(const float4*)(b1p0 + (K0)); bv1[1] = *(const float4*)(b1p1 + (K0)); \
        bv3[0] = *(const float4*)(b3p0 + (K0)); bv3[1] = *(const float4*)(b3p1 + (K0)); \
    } while (0)

    SWLOADS(0);
    for (int k0 = 0; k0 < DDIM; k0 += 32) {
        __syncthreads();
        #pragma unroll
        for (int i = 0; i < 4; i++)
            *(uint4*)&As[arow[i]][acol[i]] =
                make_uint4(tf32u(av[i].x), tf32u(av[i].y), tf32u(av[i].z), tf32u(av[i].w));
        *(uint4*)&B1s[br][bc] =
            make_uint4(tf32u(bv1[0].x), tf32u(bv1[0].y), tf32u(bv1[0].z), tf32u(bv1[0].w));
        *(uint4*)&B1s[br + 32][bc] =
            make_uint4(tf32u(bv1[1].x), tf32u(bv1[1].y), tf32u(bv1[1].z), tf32u(bv1[1].w));
        *(uint4*)&B3s[br][bc] =
            make_uint4(tf32u(bv3[0].x), tf32u(bv3[0].y), tf32u(bv3[0].z), tf32u(bv3[0].w));
        *(uint4*)&B3s[br + 32][bc] =
            make_uint4(tf32u(bv3[1].x), tf32u(bv3[1].y), tf32u(bv3[1].z), tf32u(bv3[1].w));
        __syncthreads();
        if (k0 + 32 < DDIM) SWLOADS(k0 + 32);

        #pragma unroll
        for (int ks = 0; ks < 32; ks += 8) {
            unsigned af[2][4];
            #pragma unroll
            for (int mt = 0; mt < 2; mt++) {
                int r = wm + mt * 16 + grp;
                af[mt][0] = As[r    ][ks + qid];
                af[mt][1] = As[r + 8][ks + qid];
                af[mt][2] = As[r    ][ks + qid + 4];
                af[mt][3] = As[r + 8][ks + qid + 4];
            }
            #pragma unroll
            for (int nt = 0; nt < 4; nt++) {
                int c = wn + nt * 8 + grp;
                unsigned bf1[2] = { B1s[c][ks + qid], B1s[c][ks + qid + 4] };
                unsigned bf3[2] = { B3s[c][ks + qid], B3s[c][ks + qid + 4] };
                #pragma unroll
                for (int mt = 0; mt < 2; mt++) {
                    mma8(acc1[mt][nt], af[mt], bf1);
                    mma8(acc3[mt][nt], af[mt], bf3);
                }
            }
        }
    }
    #undef SWLOADS

    #pragma unroll
    for (int mt = 0; mt < 2; mt++) {
        #pragma unroll
        for (int nt = 0; nt < 4; nt++) {
            int mlo = m0 + wm + mt * 16 + grp;
            int mhi = mlo + 8;
            int n   = n0 + wn + nt * 8 + qid * 2;
            if (mlo < cnt) {
                float g0 = acc1[mt][nt][0], g1 = acc1[mt][nt][1];
                float v0 = g0 / (1.f + expf(-g0)) * acc3[mt][nt][0];
                float v1 = g1 / (1.f + expf(-g1)) * acc3[mt][nt][1];
                *(float2*)(actout + (size_t)mlo * IDIM + n) = make_float2(v0, v1);
            }
            if (mhi < cnt) {
                float g2 = acc1[mt][nt][2], g3 = acc1[mt][nt][3];
                float v2 = g2 / (1.f + expf(-g2)) * acc3[mt][nt][2];
                float v3 = g3 / (1.f + expf(-g3)) * acc3[mt][nt][3];
                *(float2*)(actout + (size_t)mhi * IDIM + n) = make_float2(v2, v3);
            }
        }
    }
}

// ---------------- phase B: down proj via tensor-core tf32 mma -------------------
// tile 128(m) x 64(n over D), BK=32 over I
template<bool SHARED>
__global__ void __launch_bounds__(256)
down_mma(const float* __restrict__ w2, float* __restrict__ out)
{
    int e   = SHARED ? 0 : blockIdx.z;
    int cnt = SHARED ? TTOK : g_cnt[e];
    int m0  = blockIdx.y * 128;
    if (m0 >= cnt) return;
    int n0  = blockIdx.x * 64;

    const float* W2    = w2 + (SHARED ? 0 : (size_t)e * DDIM * IDIM);
    const float* actin = SHARED ? g_act_sh : (g_act + (size_t)g_off[e] * IDIM);

    __shared__ unsigned As[128][LDP];
    __shared__ unsigned Bs[64][LDP];

    int tid  = threadIdx.x;
    int lane = tid & 31, wid = tid >> 5;
    int wm = (wid & 3) * 32, wn = (wid >> 2) * 32;
    int grp = lane >> 2, qid = lane & 3;

    const float* aptr[4]; bool aval[4]; int arow[4], acol[4];
    #pragma unroll
    for (int i = 0; i < 4; i++) {
        int idx = tid + i * 256;
        int r = idx >> 3, c = (idx & 7) * 4;
        aval[i] = (m0 + r) < cnt;
        aptr[i] = actin + (size_t)(m0 + r) * IDIM + c;
        arow[i] = r; acol[i] = c;
    }
    int br = tid >> 3, bc = (tid & 7) * 4;
    const float* bp0 = W2 + (size_t)(n0 + br) * IDIM + bc;
    const float* bp1 = bp0 + (size_t)32 * IDIM;

    float acc[2][4][4];
    #pragma unroll
    for (int mt = 0; mt < 2; mt++)
        #pragma unroll
        for (int nt = 0; nt < 4; nt++)
            #pragma unroll
            for (int i = 0; i < 4; i++) acc[mt][nt][i] = 0.f;

    float4 av[4], bv[2];
    #define DNLOADS(K0) do { \
        av[0] = aval[0] ? *(const float4*)(aptr[0] + (K0)) : make_float4(0.f,0.f,0.f,0.f); \
        av[1] = aval[1] ? *(const float4*)(aptr[1] + (K0)) : make_float4(0.f,0.f,0.f,0.f); \
        av[2] = aval[2] ? *(const float4*)(aptr[2] + (K0)) : make_float4(0.f,0.f,0.f,0.f); \
        av[3] = aval[3] ? *(const float4*)(aptr[3] + (K0)) : make_float4(0.f,0.f,0.f,0.f); \
        bv[0] = *(const float4*)(bp0 + (K0)); bv[1] = *(const float4*)(bp1 + (K0)); \
    } while (0)

    DNLOADS(0);
    for (int k0 = 0; k0 < IDIM; k0 += 32) {
        __syncthreads();
        #pragma unroll
        for (int i = 0; i < 4; i++)
            *(uint4*)&As[arow[i]][acol[i]] =
                make_uint4(tf32u(av[i].x), tf32u(av[i].y), tf32u(av[i].z), tf32u(av[i].w));
        *(uint4*)&Bs[br][bc] =
            make_uint4(tf32u(bv[0].x), tf32u(bv[0].y), tf32u(bv[0].z), tf32u(bv[0].w));
        *(uint4*)&Bs[br + 32][bc] =
            make_uint4(tf32u(bv[1].x), tf32u(bv[1].y), tf32u(bv[1].z), tf32u(bv[1].w));
        __syncthreads();
        if (k0 + 32 < IDIM) DNLOADS(k0 + 32);

        #pragma unroll
        for (int ks = 0; ks < 32; ks += 8) {
            unsigned af[2][4];
            #pragma unroll
            for (int mt = 0; mt < 2; mt++) {
                int r = wm + mt * 16 + grp;
                af[mt][0] = As[r    ][ks + qid];
                af[mt][1] = As[r + 8][ks + qid];
                af[mt][2] = As[r    ][ks + qid + 4];
                af[mt][3] = As[r + 8][ks + qid + 4];
            }
            #pragma unroll
            for (int nt = 0; nt < 4; nt++) {
                int c = wn + nt * 8 + grp;
                unsigned bf[2] = { Bs[c][ks + qid], Bs[c][ks + qid + 4] };
                #pragma unroll
                for (int mt = 0; mt < 2; mt++)
                    mma8(acc[mt][nt], af[mt], bf);
            }
        }
    }
    #undef DNLOADS

    #pragma unroll
    for (int mt = 0; mt < 2; mt++) {
        int mlo = m0 + wm + mt * 16 + grp;
        int mhi = mlo + 8;
        if (SHARED) {
            #pragma unroll
            for (int nt = 0; nt < 4; nt++) {
                int n = n0 + wn + nt * 8 + qid * 2;
                if (mlo < cnt)
                    *(float2*)(out + (size_t)mlo * DDIM + n) =
                        make_float2(acc[mt][nt][0], acc[mt][nt][1]);
                if (mhi < cnt)
                    *(float2*)(out + (size_t)mhi * DDIM + n) =
                        make_float2(acc[mt][nt][2], acc[mt][nt][3]);
            }
        } else {
            int tlo = 0, thi = 0; float wlo = 0.f, whi = 0.f;
            if (mlo < cnt) { tlo = g_tok[e][mlo]; wlo = g_wt[e][mlo]; }
            if (mhi < cnt) { thi = g_tok[e][mhi]; whi = g_wt[e][mhi]; }
            #pragma unroll
            for (int nt = 0; nt < 4; nt++) {
                int n = n0 + wn + nt * 8 + qid * 2;
                if (mlo < cnt) {
                    float* o = out + (size_t)tlo * DDIM + n;
                    atomicAdd(o,     wlo * acc[mt][nt][0]);
                    atomicAdd(o + 1, wlo * acc[mt][nt][1]);
                }
                if (mhi < cnt) {
                    float* o = out + (size_t)thi * DDIM + n;
                    atomicAdd(o,     whi * acc[mt][nt][2]);
                    atomicAdd(o + 1, whi * acc[mt][nt][3]);
                }
            }
        }
    }
}

// ---------------- launch ----------------
extern "C" void kernel_launch(void* const* d_in, const int* in_sizes, int n_in,
                              void* d_out, int out_size)
{
    const float* x   = (const float*)d_in[0];
    const float* gw  = (const float*)d_in[1];
    const float* eb  = (const float*)d_in[2];
    const float* w1  = (const float*)d_in[3];
    const float* w2  = (const float*)d_in[4];
    const float* w3  = (const float*)d_in[5];
    const float* sw1 = (const float*)d_in[6];
    const float* sw2 = (const float*)d_in[7];
    const float* sw3 = (const float*)d_in[8];
    float* out = (float*)d_out;

    float* act_sh_ptr = nullptr;
    cudaGetSymbolAddress((void**)&act_sh_ptr, g_act_sh);

    zero_kernel<<<1, 32>>>();
    gate_kernel<<<TTOK, 128>>>(x, gw, eb);
    offs_kernel<<<1, 1>>>();

    // shared expert first (plain stores -> initializes out fully)
    swiglu_mma<true><<<dim3(IDIM / 64, TTOK / 128, 1), 256>>>(x, sw1, sw3, act_sh_ptr);
    down_mma<true><<<dim3(DDIM / 64, TTOK / 128, 1), 256>>>(sw2, out);

    // routed experts (atomicAdd on top)
    swiglu_mma<false><<<dim3(IDIM / 64, TTOK / 128, NEXP), 256>>>(x, w1, w3, nullptr);
    down_mma<false><<<dim3(DDIM / 64, TTOK / 128, NEXP), 256>>>(w2, out);
}

// round 9
// speedup vs baseline: 3.5615x; 1.1786x over previous
#include <cuda_runtime.h>
#include <math.h>

#define TTOK 1024
#define DDIM 2048
#define IDIM 1024
#define NEXP 32
#define KSEL 8
#define NGRP 8
#define GSZ  4
#define TOPG 4
#define SCAL 2.5f
#define LDP  36   // smem leading dim (u32): conflict-free frags, 16B-aligned rows

// tf32 truncation (RZ) — gate logits path
__device__ __forceinline__ float tf32z(float x) {
    return __uint_as_float(__float_as_uint(x) & 0xFFFFE000u);
}
// raw f32 bits -> tf32 RNA bits (expert GEMM operands, cuBLAS-style)
__device__ __forceinline__ unsigned cvtu(unsigned x) {
    unsigned r;
    asm("cvt.rna.tf32.f32 %0, %1;" : "=r"(r) : "f"(__uint_as_float(x)));
    return r;
}

__device__ __forceinline__ void mma8(float c[4], const unsigned a[4], const unsigned b[2]) {
    asm volatile("mma.sync.aligned.m16n8k8.row.col.f32.tf32.tf32.f32 "
        "{%0,%1,%2,%3}, {%4,%5,%6,%7}, {%8,%9}, {%0,%1,%2,%3};"
        : "+f"(c[0]), "+f"(c[1]), "+f"(c[2]), "+f"(c[3])
        : "r"(a[0]), "r"(a[1]), "r"(a[2]), "r"(a[3]), "r"(b[0]), "r"(b[1]));
}

#define CPA(dst_off_u32, src, vld) \
    asm volatile("cp.async.cg.shared.global [%0], [%1], 16, %2;" :: \
        "r"(smem_u32 + (unsigned)((dst_off_u32) * 4)), "l"(src), "r"((vld) ? 16 : 0))
#define CPCOMMIT() asm volatile("cp.async.commit_group;")

// ---------------- scratch ----------------
__device__ int   g_cnt[NEXP];
__device__ int   g_off[NEXP];
__device__ int   g_tok[NEXP][TTOK];
__device__ float g_wt [NEXP][TTOK];
__device__ float g_act[(size_t)KSEL * TTOK * IDIM];
__device__ float g_act_sh[(size_t)TTOK * IDIM];

__global__ void zero_kernel() {
    int i = threadIdx.x;
    if (i < NEXP) g_cnt[i] = 0;
}
__global__ void offs_kernel() {
    if (threadIdx.x == 0) {
        int s = 0;
        for (int e = 0; e < NEXP; e++) { g_off[e] = s; s += g_cnt[e]; }
    }
}
__global__ void zeroout_kernel(float4* out) {
    out[blockIdx.x * blockDim.x + threadIdx.x] = make_float4(0.f, 0.f, 0.f, 0.f);
}

// ---------------- gate / routing (RZ-tf32 logits) — unchanged, proven ----------
__global__ void gate_kernel(const float* __restrict__ x,
                            const float* __restrict__ gw,
                            const float* __restrict__ ebias)
{
    __shared__ float xs[DDIM];
    __shared__ float sc[NEXP];
    int t = blockIdx.x;
    const float* xr = x + (size_t)t * DDIM;
    for (int d = threadIdx.x; d < DDIM; d += blockDim.x) xs[d] = tf32z(xr[d]);
    __syncthreads();

    int warp = threadIdx.x >> 5, lane = threadIdx.x & 31;
    for (int e = warp; e < NEXP; e += 4) {
        const float* w = gw + (size_t)e * DDIM;
        float s = 0.f;
        for (int d = lane; d < DDIM; d += 32) s += xs[d] * tf32z(w[d]);
        #pragma unroll
        for (int o = 16; o; o >>= 1) s += __shfl_xor_sync(0xffffffffu, s, o);
        if (lane == 0) sc[e] = 1.f / (1.f + expf(-s));
    }
    __syncthreads();

    if (threadIdx.x == 0) {
        float sfc[NEXP];
        #pragma unroll
        for (int e = 0; e < NEXP; e++) sfc[e] = sc[e] + ebias[e];

        float gs[NGRP];
        for (int g = 0; g < NGRP; g++) {
            float vv[4] = { sfc[g*GSZ+0], sfc[g*GSZ+1], sfc[g*GSZ+2], sfc[g*GSZ+3] };
            float m1 = fmaxf(fmaxf(vv[0], vv[1]), fmaxf(vv[2], vv[3]));
            float s2 = -1e30f; bool used = false;
            for (int j = 0; j < 4; j++) {
                if (!used && vv[j] == m1) { used = true; continue; }
                s2 = fmaxf(s2, vv[j]);
            }
            gs[g] = m1 + s2;
        }

        bool gmask[NGRP];
        for (int g = 0; g < NGRP; g++) gmask[g] = false;
        for (int k = 0; k < TOPG; k++) {
            int bi = -1; float bv = -1e30f;
            for (int g = 0; g < NGRP; g++)
                if (!gmask[g] && gs[g] > bv) { bv = gs[g]; bi = g; }
            gmask[bi] = true;
        }

        float mv[NEXP];
        for (int e = 0; e < NEXP; e++) mv[e] = gmask[e / GSZ] ? sfc[e] : 0.f;

        int   idx[KSEL]; float tw[KSEL]; float tsum = 0.f;
        for (int k = 0; k < KSEL; k++) {
            int bi = 0; float bv = -1e30f;
            for (int e = 0; e < NEXP; e++)
                if (mv[e] > bv) { bv = mv[e]; bi = e; }
            mv[bi] = -1e30f;
            idx[k] = bi;
            tw[k]  = sc[bi];
            tsum  += sc[bi];
        }
        float inv = SCAL / (tsum + 1e-20f);
        for (int k = 0; k < KSEL; k++) {
            int e = idx[k];
            int slot = atomicAdd(&g_cnt[e], 1);
            g_tok[e][slot] = t;
            g_wt [e][slot] = tw[k] * inv;
        }
    }
}

// ---------------- phase A: SwiGLU up, cp.async double-buffered tf32 mma ---------
// tile 128(m) x 64(n), BK=32; z = 0..32 (32 = shared expert)
__global__ void __launch_bounds__(256, 2)
swiglu_mma(const float* __restrict__ x,
           const float* __restrict__ w1,  const float* __restrict__ w3,
           const float* __restrict__ sw1, const float* __restrict__ sw3,
           float* __restrict__ act_sh)
{
    int e = blockIdx.z;
    bool she = (e == NEXP);
    int cnt = she ? TTOK : g_cnt[e];
    int m0  = blockIdx.y * 128;
    if (m0 >= cnt) return;
    int n0  = blockIdx.x * 64;

    const float* W1 = she ? sw1 : w1 + (size_t)e * IDIM * DDIM;
    const float* W3 = she ? sw3 : w3 + (size_t)e * IDIM * DDIM;
    float* actout   = she ? act_sh : g_act + (size_t)g_off[e] * IDIM;

    extern __shared__ unsigned smemraw[];
    // layout: A[2][128][LDP], B1[2][64][LDP], B3[2][64][LDP]
    const unsigned OFF_B1 = 2 * 128 * LDP;
    const unsigned OFF_B3 = OFF_B1 + 2 * 64 * LDP;
    unsigned smem_u32 = (unsigned)__cvta_generic_to_shared(smemraw);

    int tid  = threadIdx.x;
    int lane = tid & 31, wid = tid >> 5;
    int wm = (wid & 3) * 32, wn = (wid >> 2) * 32;
    int grp = lane >> 2, qid = lane & 3;

    // A gather setup: 4 chunks/thread
    const float* aptr[4]; bool aval[4]; int aoff[4];
    #pragma unroll
    for (int i = 0; i < 4; i++) {
        int idx = tid + i * 256;
        int r = idx >> 3, c = (idx & 7) * 4;
        int m = m0 + r;
        bool v = m < cnt;
        int tok = 0;
        if (v) tok = she ? m : g_tok[e][m];
        aptr[i] = x + (size_t)tok * DDIM + c;
        aval[i] = v;
        aoff[i] = r * LDP + c;
    }
    int br = tid >> 3, bc = (tid & 7) * 4;
    const float* b1p0 = W1 + (size_t)(n0 + br) * DDIM + bc;
    const float* b1p1 = b1p0 + (size_t)32 * DDIM;
    const float* b3p0 = W3 + (size_t)(n0 + br) * DDIM + bc;
    const float* b3p1 = b3p0 + (size_t)32 * DDIM;
    int boff0 = br * LDP + bc, boff1 = (br + 32) * LDP + bc;

    #define SWLOAD(buf, K0) do { \
        unsigned ab = (buf) * 128 * LDP; \
        CPA(ab + aoff[0], aptr[0] + (K0), aval[0]); \
        CPA(ab + aoff[1], aptr[1] + (K0), aval[1]); \
        CPA(ab + aoff[2], aptr[2] + (K0), aval[2]); \
        CPA(ab + aoff[3], aptr[3] + (K0), aval[3]); \
        unsigned b1b = OFF_B1 + (buf) * 64 * LDP; \
        unsigned b3b = OFF_B3 + (buf) * 64 * LDP; \
        CPA(b1b + boff0, b1p0 + (K0), 1); \
        CPA(b1b + boff1, b1p1 + (K0), 1); \
        CPA(b3b + boff0, b3p0 + (K0), 1); \
        CPA(b3b + boff1, b3p1 + (K0), 1); \
        CPCOMMIT(); \
    } while (0)

    float acc1[2][4][4], acc3[2][4][4];
    #pragma unroll
    for (int mt = 0; mt < 2; mt++)
        #pragma unroll
        for (int nt = 0; nt < 4; nt++)
            #pragma unroll
            for (int i = 0; i < 4; i++) { acc1[mt][nt][i] = 0.f; acc3[mt][nt][i] = 0.f; }

    const int NSLAB = DDIM / 32;
    SWLOAD(0, 0);
    for (int s = 0; s < NSLAB; s++) {
        if (s + 1 < NSLAB) {
            SWLOAD((s + 1) & 1, (s + 1) * 32);
            asm volatile("cp.async.wait_group 1;");
        } else {
            asm volatile("cp.async.wait_group 0;");
        }
        __syncthreads();

        int buf = s & 1;
        const unsigned* Ab  = smemraw + buf * 128 * LDP;
        const unsigned* B1b = smemraw + OFF_B1 + buf * 64 * LDP;
        const unsigned* B3b = smemraw + OFF_B3 + buf * 64 * LDP;
        #pragma unroll
        for (int ks = 0; ks < 32; ks += 8) {
            unsigned af[2][4];
            #pragma unroll
            for (int mt = 0; mt < 2; mt++) {
                int r = wm + mt * 16 + grp;
                af[mt][0] = cvtu(Ab[r * LDP + ks + qid]);
                af[mt][1] = cvtu(Ab[(r + 8) * LDP + ks + qid]);
                af[mt][2] = cvtu(Ab[r * LDP + ks + qid + 4]);
                af[mt][3] = cvtu(Ab[(r + 8) * LDP + ks + qid + 4]);
            }
            #pragma unroll
            for (int nt = 0; nt < 4; nt++) {
                int c = wn + nt * 8 + grp;
                unsigned bf1[2] = { cvtu(B1b[c * LDP + ks + qid]), cvtu(B1b[c * LDP + ks + qid + 4]) };
                unsigned bf3[2] = { cvtu(B3b[c * LDP + ks + qid]), cvtu(B3b[c * LDP + ks + qid + 4]) };
                #pragma unroll
                for (int mt = 0; mt < 2; mt++) {
                    mma8(acc1[mt][nt], af[mt], bf1);
                    mma8(acc3[mt][nt], af[mt], bf3);
                }
            }
        }
        __syncthreads();
    }
    #undef SWLOAD

    #pragma unroll
    for (int mt = 0; mt < 2; mt++) {
        #pragma unroll
        for (int nt = 0; nt < 4; nt++) {
            int mlo = m0 + wm + mt * 16 + grp;
            int mhi = mlo + 8;
            int n   = n0 + wn + nt * 8 + qid * 2;
            if (mlo < cnt) {
                float g0 = acc1[mt][nt][0], g1 = acc1[mt][nt][1];
                float v0 = g0 / (1.f + expf(-g0)) * acc3[mt][nt][0];
                float v1 = g1 / (1.f + expf(-g1)) * acc3[mt][nt][1];
                *(float2*)(actout + (size_t)mlo * IDIM + n) = make_float2(v0, v1);
            }
            if (mhi < cnt) {
                float g2 = acc1[mt][nt][2], g3 = acc1[mt][nt][3];
                float v2 = g2 / (1.f + expf(-g2)) * acc3[mt][nt][2];
                float v3 = g3 / (1.f + expf(-g3)) * acc3[mt][nt][3];
                *(float2*)(actout + (size_t)mhi * IDIM + n) = make_float2(v2, v3);
            }
        }
    }
}

// ---------------- phase B: down proj, cp.async double-buffered tf32 mma ---------
__global__ void __launch_bounds__(256, 2)
down_mma(const float* __restrict__ w2, const float* __restrict__ sw2,
         const float* __restrict__ act_sh, float* __restrict__ out)
{
    int e = blockIdx.z;
    bool she = (e == NEXP);
    int cnt = she ? TTOK : g_cnt[e];
    int m0  = blockIdx.y * 128;
    if (m0 >= cnt) return;
    int n0  = blockIdx.x * 64;

    const float* W2    = she ? sw2 : w2 + (size_t)e * DDIM * IDIM;
    const float* actin = she ? act_sh : g_act + (size_t)g_off[e] * IDIM;

    extern __shared__ unsigned smemraw[];
    const unsigned OFF_B = 2 * 128 * LDP;
    unsigned smem_u32 = (unsigned)__cvta_generic_to_shared(smemraw);

    int tid  = threadIdx.x;
    int lane = tid & 31, wid = tid >> 5;
    int wm = (wid & 3) * 32, wn = (wid >> 2) * 32;
    int grp = lane >> 2, qid = lane & 3;

    const float* aptr[4]; bool aval[4]; int aoff[4];
    #pragma unroll
    for (int i = 0; i < 4; i++) {
        int idx = tid + i * 256;
        int r = idx >> 3, c = (idx & 7) * 4;
        aval[i] = (m0 + r) < cnt;
        aptr[i] = actin + (size_t)(m0 + r) * IDIM + c;
        aoff[i] = r * LDP + c;
    }
    int br = tid >> 3, bc = (tid & 7) * 4;
    const float* bp0 = W2 + (size_t)(n0 + br) * IDIM + bc;
    const float* bp1 = bp0 + (size_t)32 * IDIM;
    int boff0 = br * LDP + bc, boff1 = (br + 32) * LDP + bc;

    #define DNLOAD(buf, K0) do { \
        unsigned ab = (buf) * 128 * LDP; \
        CPA(ab + aoff[0], aptr[0] + (K0), aval[0]); \
        CPA(ab + aoff[1], aptr[1] + (K0), aval[1]); \
        CPA(ab + aoff[2], aptr[2] + (K0), aval[2]); \
        CPA(ab + aoff[3], aptr[3] + (K0), aval[3]); \
        unsigned bb = OFF_B + (buf) * 64 * LDP; \
        CPA(bb + boff0, bp0 + (K0), 1); \
        CPA(bb + boff1, bp1 + (K0), 1); \
        CPCOMMIT(); \
    } while (0)

    float acc[2][4][4];
    #pragma unroll
    for (int mt = 0; mt < 2; mt++)
        #pragma unroll
        for (int nt = 0; nt < 4; nt++)
            #pragma unroll
            for (int i = 0; i < 4; i++) acc[mt][nt][i] = 0.f;

    const int NSLAB = IDIM / 32;
    DNLOAD(0, 0);
    for (int s = 0; s < NSLAB; s++) {
        if (s + 1 < NSLAB) {
            DNLOAD((s + 1) & 1, (s + 1) * 32);
            asm volatile("cp.async.wait_group 1;");
        } else {
            asm volatile("cp.async.wait_group 0;");
        }
        __syncthreads();

        int buf = s & 1;
        const unsigned* Ab = smemraw + buf * 128 * LDP;
        const unsigned* Bb = smemraw + OFF_B + buf * 64 * LDP;
        #pragma unroll
        for (int ks = 0; ks < 32; ks += 8) {
            unsigned af[2][4];
            #pragma unroll
            for (int mt = 0; mt < 2; mt++) {
                int r = wm + mt * 16 + grp;
                af[mt][0] = cvtu(Ab[r * LDP + ks + qid]);
                af[mt][1] = cvtu(Ab[(r + 8) * LDP + ks + qid]);
                af[mt][2] = cvtu(Ab[r * LDP + ks + qid + 4]);
                af[mt][3] = cvtu(Ab[(r + 8) * LDP + ks + qid + 4]);
            }
            #pragma unroll
            for (int nt = 0; nt < 4; nt++) {
                int c = wn + nt * 8 + grp;
                unsigned bf[2] = { cvtu(Bb[c * LDP + ks + qid]), cvtu(Bb[c * LDP + ks + qid + 4]) };
                #pragma unroll
                for (int mt = 0; mt < 2; mt++)
                    mma8(acc[mt][nt], af[mt], bf);
            }
        }
        __syncthreads();
    }
    #undef DNLOAD

    #pragma unroll
    for (int mt = 0; mt < 2; mt++) {
        int mlo = m0 + wm + mt * 16 + grp;
        int mhi = mlo + 8;
        int tlo = 0, thi = 0; float wlo = 0.f, whi = 0.f;
        if (mlo < cnt) { tlo = she ? mlo : g_tok[e][mlo]; wlo = she ? 1.f : g_wt[e][mlo]; }
        if (mhi < cnt) { thi = she ? mhi : g_tok[e][mhi]; whi = she ? 1.f : g_wt[e][mhi]; }
        #pragma unroll
        for (int nt = 0; nt < 4; nt++) {
            int n = n0 + wn + nt * 8 + qid * 2;
            if (mlo < cnt) {
                float* o = out + (size_t)tlo * DDIM + n;
                atomicAdd(o,     wlo * acc[mt][nt][0]);
                atomicAdd(o + 1, wlo * acc[mt][nt][1]);
            }
            if (mhi < cnt) {
                float* o = out + (size_t)thi * DDIM + n;
                atomicAdd(o,     whi * acc[mt][nt][2]);
                atomicAdd(o + 1, whi * acc[mt][nt][3]);
            }
        }
    }
}

// ---------------- launch ----------------
extern "C" void kernel_launch(void* const* d_in, const int* in_sizes, int n_in,
                              void* d_out, int out_size)
{
    const float* x   = (const float*)d_in[0];
    const float* gw  = (const float*)d_in[1];
    const float* eb  = (const float*)d_in[2];
    const float* w1  = (const float*)d_in[3];
    const float* w2  = (const float*)d_in[4];
    const float* w3  = (const float*)d_in[5];
    const float* sw1 = (const float*)d_in[6];
    const float* sw2 = (const float*)d_in[7];
    const float* sw3 = (const float*)d_in[8];
    float* out = (float*)d_out;

    const int SW_SMEM = 2 * (128 + 64 + 64) * LDP * 4;   // 73728
    const int DN_SMEM = 2 * (128 + 64) * LDP * 4;        // 55296
    cudaFuncSetAttribute(swiglu_mma, cudaFuncAttributeMaxDynamicSharedMemorySize, SW_SMEM);
    cudaFuncSetAttribute(down_mma,   cudaFuncAttributeMaxDynamicSharedMemorySize, DN_SMEM);

    float* act_sh_ptr = nullptr;
    cudaGetSymbolAddress((void**)&act_sh_ptr, g_act_sh);

    zero_kernel<<<1, 32>>>();
    gate_kernel<<<TTOK, 128>>>(x, gw, eb);
    offs_kernel<<<1, 1>>>();
    zeroout_kernel<<<(TTOK * DDIM / 4) / 256, 256>>>((float4*)out);

    // all experts incl. shared (z = 32) in two launches
    swiglu_mma<<<dim3(IDIM / 64, TTOK / 128, NEXP + 1), 256, SW_SMEM>>>(
        x, w1, w3, sw1, sw3, act_sh_ptr);
    down_mma<<<dim3(DDIM / 64, TTOK / 128, NEXP + 1), 256, DN_SMEM>>>(
        w2, sw2, act_sh_ptr, out);
}